// round 10
// baseline (speedup 1.0000x reference)
#include <cuda_runtime.h>
#include <cuda_fp16.h>
#include <cstdint>

#define NCq   100
#define NCPAD 104
#define NBLKS 128
#define PADH  136      /* Ah / Xh / Wh / Ct stride (halves) */

// ---- static device scratch (no allocations allowed) ----
__device__ __align__(16) float g_Spart[128 * NBLKS];          // [b][kb]
__device__ __align__(16) float g_Opart[128 * NBLKS * NCPAD];  // [b][kb][104]
__device__ int g_bar1 = 0;
__device__ int g_bar2 = 0;

// smem layout (bytes)
#define AH_OFFB  0                                /* 128*136*2 = 34816 */
#define XH_OFFB  34816                            /* 34816 */
#define CT_OFFB  69632                            /* 112*136*2 = 30464 */
#define X2_OFFB  100096                           /* 512 */
#define Y2_OFFB  100608                           /* 512 */
#define PX_OFFB  101120                           /* 512 */
#define PY_OFFB  101632                           /* 512 */
#define SMEM_BYTES 102144
/* Wh (fp16 [b][n]) aliases Ah after GEMM1; reduce scratch aliases Ah after GEMM2 */

// ============================ helpers ============================
__device__ __forceinline__ float fsqrt_ap(float x) {
    float r; asm("sqrt.approx.f32 %0, %1;" : "=f"(r) : "f"(x)); return r;
}
__device__ __forceinline__ float frsqrt_ap(float x) {
    float r; asm("rsqrt.approx.f32 %0, %1;" : "=f"(r) : "f"(x)); return r;
}
__device__ __forceinline__ uint2 pack4h(float4 v) {
    __half2 h01 = __floats2half2_rn(v.x, v.y);
    __half2 h23 = __floats2half2_rn(v.z, v.w);
    uint2 u;
    u.x = *(uint32_t*)&h01;
    u.y = *(uint32_t*)&h23;
    return u;
}
// fp16 m16n8k16: D(f32) += A(f16) * B(f16)
__device__ __forceinline__ void mma16(float* d, uint32_t a0, uint32_t a1,
                                      uint32_t a2, uint32_t a3,
                                      uint32_t b0, uint32_t b1) {
    asm volatile(
        "mma.sync.aligned.m16n8k16.row.col.f32.f16.f16.f32 "
        "{%0,%1,%2,%3}, {%4,%5,%6,%7}, {%8,%9}, {%0,%1,%2,%3};"
        : "+f"(d[0]), "+f"(d[1]), "+f"(d[2]), "+f"(d[3])
        : "r"(a0), "r"(a1), "r"(a2), "r"(a3), "r"(b0), "r"(b1));
}

// ============================ main kernel ============================
__global__ __launch_bounds__(512, 1)
void main_kernel(const float* __restrict__ X, const float* __restrict__ A,
                 const float* __restrict__ C, float* __restrict__ out) {
    extern __shared__ __align__(16) char smb[];
    __half* Ah   = (__half*)(smb + AH_OFFB);      // [n][k] fp16, stride PADH
    __half* Xh   = (__half*)(smb + XH_OFFB);      // [b][k] fp16, stride PADH
    __half* Ct   = (__half*)(smb + CT_OFFB);      // [c][n] fp16, stride PADH (c<112)
    float*  x2s  = (float*)(smb + X2_OFFB);
    float*  y2s  = (float*)(smb + Y2_OFFB);
    float*  px4s = (float*)(smb + PX_OFFB);       // (1-x2)^(1/4)
    float*  py4s = (float*)(smb + PY_OFFB);       // (1-y2)^(1/4)
    __half* Wh   = (__half*)(smb + AH_OFFB);      // later: [b][n] fp16 (aliases Ah)

    const int tid = threadIdx.x;
    const int w   = tid >> 5;        // 0..15
    const int l   = tid & 31;
    const int g   = l >> 2;          // 0..7
    const int tg  = l & 3;           // 0..3
    const int n0  = blockIdx.x * 128;

    // ---------------- load + project + convert (8 iters, 16 rows/iter) ----------------
#pragma unroll
    for (int it = 0; it < 8; it++) {
        const int r = it * 16 + w;
        // A row -> Ah[r][*] (fp16), x2 + px4
        float4 va = ((const float4*)(A + (size_t)(n0 + r) * 128))[l];
        float sa = va.x * va.x + va.y * va.y + va.z * va.z + va.w * va.w;
#pragma unroll
        for (int off = 16; off > 0; off >>= 1)
            sa += __shfl_xor_sync(0xffffffffu, sa, off);
        if (l == 0) {
            x2s[r]  = sa;
            px4s[r] = fsqrt_ap(fsqrt_ap(1.0f - sa));
        }
        *(uint2*)&Ah[r * PADH + l * 4] = pack4h(va);

        // X row -> project -> Xh[r][*] (fp16), y2 + py4
        float4 vx = ((const float4*)(X + (size_t)r * 128))[l];
        float sx = vx.x * vx.x + vx.y * vx.y + vx.z * vx.z + vx.w * vx.w;
#pragma unroll
        for (int off = 16; off > 0; off >>= 1)
            sx += __shfl_xor_sync(0xffffffffu, sx, off);
        float norm  = fmaxf(sqrtf(sx), 1e-15f);
        const float maxn = 1.0f - 4e-3f;
        float scale = (norm > maxn) ? (maxn / norm) : 1.0f;
        if (l == 0) {
            float y2 = sx * scale * scale;
            y2s[r]  = y2;
            py4s[r] = fsqrt_ap(fsqrt_ap(1.0f - y2));
        }
        vx.x *= scale; vx.y *= scale; vx.z *= scale; vx.w *= scale;
        *(uint2*)&Xh[r * PADH + l * 4] = pack4h(vx);

        // C row (n0+r) -> transposed Ct[c][n=r] (fp16); c=100 ones, 101..111 zero
        if (l < 28) {
            float4 vc = make_float4(0.f, 0.f, 0.f, 0.f);
            if (l < 25)       vc = ((const float4*)(C + (size_t)(n0 + r) * NCq))[l];
            else if (l == 25) vc = make_float4(1.0f, 0.f, 0.f, 0.f);
            Ct[(l * 4 + 0) * PADH + r] = __float2half_rn(vc.x);
            Ct[(l * 4 + 1) * PADH + r] = __float2half_rn(vc.y);
            Ct[(l * 4 + 2) * PADH + r] = __float2half_rn(vc.z);
            Ct[(l * 4 + 3) * PADH + r] = __float2half_rn(vc.w);
        }
    }
    __syncthreads();

    // ---------------- GEMM1 (fp16): D1[n][b] = A @ Xp^T ----------------
    // 16 warps in 4x4 grid: each warp 32n x 32b
    const int wn = w >> 2, wb = w & 3;
    const __half* Abh = Ah + (wn * 32) * PADH;
    const __half* Xbh = Xh + (wb * 32) * PADH;

    float acc[2][4][4];
#pragma unroll
    for (int mt = 0; mt < 2; mt++)
#pragma unroll
        for (int bt = 0; bt < 4; bt++)
#pragma unroll
            for (int rr = 0; rr < 4; rr++) acc[mt][bt][rr] = 0.f;

#pragma unroll
    for (int ks = 0; ks < 8; ks++) {
        const int k0 = ks * 16 + 2 * tg;
        uint32_t a0[2], a1[2], a2[2], a3[2];
#pragma unroll
        for (int mt = 0; mt < 2; mt++) {
            a0[mt] = *(const uint32_t*)&Abh[(mt * 16 + g)     * PADH + k0];
            a1[mt] = *(const uint32_t*)&Abh[(mt * 16 + 8 + g) * PADH + k0];
            a2[mt] = *(const uint32_t*)&Abh[(mt * 16 + g)     * PADH + k0 + 8];
            a3[mt] = *(const uint32_t*)&Abh[(mt * 16 + 8 + g) * PADH + k0 + 8];
        }
#pragma unroll
        for (int bt = 0; bt < 4; bt++) {
            uint32_t b0 = *(const uint32_t*)&Xbh[(bt * 8 + g) * PADH + k0];
            uint32_t b1 = *(const uint32_t*)&Xbh[(bt * 8 + g) * PADH + k0 + 8];
            mma16(acc[0][bt], a0[0], a1[0], a2[0], a3[0], b0, b1);
            mma16(acc[1][bt], a0[1], a1[1], a2[1], a3[1], b0, b1);
        }
    }

    // ---------------- epilogue: dot -> w ----------------
    // w = (PxPy)^(1/4) * rsqrt(sqrt(den) + sqrt(||x-y||^2)); PxPy^(1/4) from smem
    float x2v[4], px4[4];
#pragma unroll
    for (int mt = 0; mt < 2; mt++)
#pragma unroll
        for (int h = 0; h < 2; h++) {
            const int nn = wn * 32 + mt * 16 + h * 8 + g;
            x2v[mt * 2 + h] = x2s[nn];
            px4[mt * 2 + h] = px4s[nn];
        }
    float y2v[8], py4[8];
#pragma unroll
    for (int bt = 0; bt < 4; bt++)
#pragma unroll
        for (int j = 0; j < 2; j++) {
            const int bb = wb * 32 + bt * 8 + 2 * tg + j;
            y2v[bt * 2 + j] = y2s[bb];
            py4[bt * 2 + j] = py4s[bb];
        }
#pragma unroll
    for (int mt = 0; mt < 2; mt++)
#pragma unroll
        for (int bt = 0; bt < 4; bt++)
#pragma unroll
            for (int rr = 0; rr < 4; rr++) {
                const int hi = rr >> 1, j = rr & 1;
                float dot = acc[mt][bt][rr];
                float x2  = x2v[mt * 2 + hi];
                float y2  = y2v[bt * 2 + j];
                float den = fmaf(x2, y2, fmaf(-2.0f, dot, 1.0f));
                float v2  = fmaxf(fmaf(-2.0f, dot, x2 + y2), 0.0f);
                float s   = fsqrt_ap(den) + fsqrt_ap(v2);
                float wq  = px4[mt * 2 + hi] * py4[bt * 2 + j] * frsqrt_ap(s);
                wq = fminf(fmaxf(wq, 0.015625f), 1.0f);
                acc[mt][bt][rr] = wq;
            }

    __syncthreads();   // all GEMM1 smem reads done before Wh overwrites Ah

    // store W transposed: Wh[b][n] (fp16, aliases Ah region)
#pragma unroll
    for (int mt = 0; mt < 2; mt++)
#pragma unroll
        for (int bt = 0; bt < 4; bt++) {
            const int nn = wn * 32 + mt * 16 + g;
            const int bb = wb * 32 + bt * 8 + 2 * tg;
            Wh[(bb)     * PADH + nn]     = __float2half_rn(acc[mt][bt][0]);
            Wh[(bb + 1) * PADH + nn]     = __float2half_rn(acc[mt][bt][1]);
            Wh[(bb)     * PADH + nn + 8] = __float2half_rn(acc[mt][bt][2]);
            Wh[(bb + 1) * PADH + nn + 8] = __float2half_rn(acc[mt][bt][3]);
        }
    __syncthreads();

    // ---------------- GEMM2 (fp16): O[b][c] = W @ Ct^T  (N=112, col100 = S) ----------------
    // 16 warps in 8x2 grid: each warp 16b x 56c; k = n (128), 8 K-steps
    const int wb2 = w >> 1, wc = w & 1;
    const __half* Wb = Wh + (wb2 * 16) * PADH;

    float acc2[7][4];
#pragma unroll
    for (int ct = 0; ct < 7; ct++)
#pragma unroll
        for (int rr = 0; rr < 4; rr++) acc2[ct][rr] = 0.f;

#pragma unroll
    for (int ks = 0; ks < 8; ks++) {
        const int k0 = ks * 16 + 2 * tg;
        uint32_t a0 = *(const uint32_t*)&Wb[(g)     * PADH + k0];
        uint32_t a1 = *(const uint32_t*)&Wb[(8 + g) * PADH + k0];
        uint32_t a2 = *(const uint32_t*)&Wb[(g)     * PADH + k0 + 8];
        uint32_t a3 = *(const uint32_t*)&Wb[(8 + g) * PADH + k0 + 8];
#pragma unroll
        for (int ct = 0; ct < 7; ct++) {
            const int col = wc * 56 + ct * 8 + g;
            uint32_t b0 = *(const uint32_t*)&Ct[col * PADH + k0];
            uint32_t b1 = *(const uint32_t*)&Ct[col * PADH + k0 + 8];
            mma16(acc2[ct], a0, a1, a2, a3, b0, b1);
        }
    }

    // ---------------- store partials: Opart[b][kb][104], Spart[b][kb] ----------------
    const int kb = blockIdx.x;
#pragma unroll
    for (int ct = 0; ct < 7; ct++) {
        const int c = wc * 56 + ct * 8 + 2 * tg;
        const int b = wb2 * 16 + g;
        if (c < NCq) {
            *(float2*)&g_Opart[((size_t)b * NBLKS + kb) * NCPAD + c] =
                make_float2(acc2[ct][0], acc2[ct][1]);
            *(float2*)&g_Opart[((size_t)(b + 8) * NBLKS + kb) * NCPAD + c] =
                make_float2(acc2[ct][2], acc2[ct][3]);
        } else if (c == NCq) {   // ones column -> softmax denominator
            g_Spart[b * NBLKS + kb]       = acc2[ct][0];
            g_Spart[(b + 8) * NBLKS + kb] = acc2[ct][2];
        }
    }

    // ---------------- grid-wide barrier (all partials visible) ----------------
    __syncthreads();
    if (tid == 0) {
        __threadfence();
        atomicAdd(&g_bar1, 1);
        while (atomicAdd(&g_bar1, 0) < NBLKS) __nanosleep(32);
        __threadfence();
    }
    __syncthreads();

    // ---------------- fused final reduction: block kb handles b = kb ----------------
    // 512 threads = 16 kb-splits x 32 lanes; float4 lanes (26 cover 104 cols).
    {
        float4* so   = (float4*)smb;                       // [16][26] (aliases Ah)
        float*  ssum = (float*)(smb + 16 * 26 * 16);       // [16]

        const int b     = blockIdx.x;
        const int split = tid >> 5;      // 0..15
        const int lane  = tid & 31;

        if (lane < 26) {
            const float4* ob =
                (const float4*)(g_Opart + ((size_t)b * NBLKS + split * 8) * NCPAD) + lane;
            float4 t0 = ob[0 * 26], t1 = ob[1 * 26], t2 = ob[2 * 26], t3 = ob[3 * 26];
            float4 u0 = ob[4 * 26], u1 = ob[5 * 26], u2 = ob[6 * 26], u3 = ob[7 * 26];
            float4 t;
            t.x = ((t0.x + u0.x) + (t1.x + u1.x)) + ((t2.x + u2.x) + (t3.x + u3.x));
            t.y = ((t0.y + u0.y) + (t1.y + u1.y)) + ((t2.y + u2.y) + (t3.y + u3.y));
            t.z = ((t0.z + u0.z) + (t1.z + u1.z)) + ((t2.z + u2.z) + (t3.z + u3.z));
            t.w = ((t0.w + u0.w) + (t1.w + u1.w)) + ((t2.w + u2.w) + (t3.w + u3.w));
            so[split * 26 + lane] = t;
        } else if (lane == 26) {
            const float* sb = g_Spart + b * NBLKS + split * 8;
            float s0 = 0.f, s1 = 0.f, s2 = 0.f, s3 = 0.f;
            s0 = sb[0] + sb[4]; s1 = sb[1] + sb[5];
            s2 = sb[2] + sb[6]; s3 = sb[3] + sb[7];
            ssum[split] = (s0 + s1) + (s2 + s3);
        }
        __syncthreads();

        if (tid < 25) {   // c = 4*tid in [0, 100)
            float4 o = make_float4(0.f, 0.f, 0.f, 0.f);
            float st = 0.f;
#pragma unroll
            for (int s2 = 0; s2 < 16; s2++) {
                float4 a = so[s2 * 26 + tid];
                o.x += a.x; o.y += a.y; o.z += a.z; o.w += a.w;
                st += ssum[s2];
            }
            float inv = 1.0f / st;
            o.x *= inv; o.y *= inv; o.z *= inv; o.w *= inv;
            *(float4*)(out + b * NCq + tid * 4) = o;
        }
    }

    // ---------------- reset barrier counters for next replay ----------------
    __syncthreads();
    if (tid == 0) {
        int old = atomicAdd(&g_bar2, 1);
        if (old == NBLKS - 1) {         // last block: everyone passed bar1 & finished
            atomicExch(&g_bar1, 0);
            atomicExch(&g_bar2, 0);
        }
    }
}

// ============================ launch ============================
extern "C" void kernel_launch(void* const* d_in, const int* in_sizes, int n_in,
                              void* d_out, int out_size) {
    (void)in_sizes; (void)n_in; (void)out_size;
    const float* X = (const float*)d_in[0];   // [128,128]
    const float* A = (const float*)d_in[1];   // [16384,1,128]
    const float* C = (const float*)d_in[2];   // [16384,100]
    float* out = (float*)d_out;               // [128,100] fp32

    cudaFuncSetAttribute(main_kernel,
                         cudaFuncAttributeMaxDynamicSharedMemorySize, SMEM_BYTES);

    main_kernel<<<NBLKS, 512, SMEM_BYTES>>>(X, A, C, out);
}